// round 10
// baseline (speedup 1.0000x reference)
#include <cuda_runtime.h>
#include <cstdint>

// ---------------- problem constants ----------------
#define BN_TOK 32768
#define DDIM   1408
#define PDIM   256
#define KC0    64
#define KC1    128
#define KC2    256
#define OUT_IDX  46137344
#define OUT_LOSS 46235648

// ---------------- device scratch ----------------
__device__ float g_zproj[BN_TOK * PDIM];
__device__ float g_R    [BN_TOK * PDIM];
__device__ float g_qcomb[BN_TOK * PDIM];
__device__ float g_nr   [BN_TOK];
__device__ float g_dmin [BN_TOK];
__device__ float g_enorm[512];
__device__ int   g_cand [8 * BN_TOK];
// pre-split (hi/lo tf32) fragment-ordered B operand images
__device__ float g_BWin [720896];   // N=256,  K=1408, NT=128
__device__ float g_BWout[720896];   // N=1408, K=256,  NT=128
__device__ float g_Be0  [32768];    // N=64,   K=256,  NT=64
__device__ float g_Be1  [65536];    // N=128,  K=256,  NT=128
__device__ float g_Be2  [131072];   // N=256,  K=256,  NT=128

// ---------------- helpers ----------------
__device__ __forceinline__ float tf32_rna(float x) {
    uint32_t u; asm("cvt.rna.tf32.f32 %0, %1;" : "=r"(u) : "f"(x));
    return __uint_as_float(u);
}
__device__ __forceinline__ void mma_tf32(float* c, const uint32_t* a, const uint32_t* b) {
    asm volatile("mma.sync.aligned.m16n8k8.row.col.f32.tf32.tf32.f32 "
        "{%0,%1,%2,%3}, {%4,%5,%6,%7}, {%8,%9}, {%0,%1,%2,%3};"
        : "+f"(c[0]), "+f"(c[1]), "+f"(c[2]), "+f"(c[3])
        : "r"(a[0]), "r"(a[1]), "r"(a[2]), "r"(a[3]), "r"(b[0]), "r"(b[1]));
}
__device__ __forceinline__ uint32_t smem_u32(const void* p) {
    uint32_t a;
    asm("{ .reg .u64 t; cvta.to.shared.u64 t, %1; cvt.u32.u64 %0, t; }" : "=r"(a) : "l"(p));
    return a;
}
__device__ __forceinline__ void cp16(uint32_t dst, const void* src) {
    asm volatile("cp.async.ca.shared.global [%0], [%1], 16;" :: "r"(dst), "l"(src));
}
#define CP_COMMIT() asm volatile("cp.async.commit_group;" ::: "memory")
#define CP_WAIT1()  asm volatile("cp.async.wait_group 1;" ::: "memory")

// insert (dv, cg) into sorted top-4 list (ascending d, index tie-break)
__device__ __forceinline__ void ins4(float* d, int* ci, float dv, int cg) {
    #pragma unroll
    for (int q = 0; q < 4; q++) {
        bool better = dv < d[q] || (dv == d[q] && cg < ci[q]);
        float td = d[q]; int ti = ci[q];
        if (better) { d[q] = dv; ci[q] = cg; dv = td; cg = ti; }
    }
}

// ---------------- B image prep ----------------
// Element decomposition identical to round-8/9 (proven). New STORE layout:
// per (nb,kb) block, per tile tl = wn*NI+ni (8 n-values x 16 k-values):
//   offset = tl*256 + s*128 + lane*4 + {0,1}=hi_w / {2,3}=lo_w
// so one float4 per (tl, s, lane) = {hi_w0, hi_w1, lo_w0, lo_w1}.
template<int NT>
__global__ void bprep(const float* __restrict__ src, float* __restrict__ img,
                      int K, int ld, int trans, int total) {
    int i = blockIdx.x * 256 + threadIdx.x;
    if (i >= total) return;
    constexpr int NI = NT / 16;
    int word = i & (NT * 16 - 1);
    int rest = i / (NT * 16);
    int kb = rest % (K / 16);
    int nb = rest / (K / 16);
    int w = word & 1;
    int t = (word >> 1) & 3;
    int g = (word >> 3) & 7;
    int s = (word >> 6) & 1;
    int tl = word >> 7;
    int wn = tl / NI, ni = tl % NI;
    int n = nb * NT + wn * (NT / 2) + ni * 8 + g;
    int k = kb * 16 + s * 8 + t + w * 4;
    float x = trans ? src[(size_t)k * ld + n] : src[(size_t)n * ld + k];
    float hi = tf32_rna(x), lo = tf32_rna(x - hi);
    size_t base = (size_t)rest * (NT * 32);
    int lane = g * 4 + t;
    int off = tl * 256 + s * 128 + lane * 4 + w;
    img[base + off]     = hi;
    img[base + off + 2] = lo;
}

// =====================================================================
// tf32 3-product warp-MMA GEMM.  CTA tile 128m x NT.  8 warps (4m x 2n),
// warp tile 32 x (NT/2).  BK=16.  A double-buffered fragment-ordered smem
// (XOR-chunk); B triple-buffered cp.async from packed hi/lo image.
// MODE 0: C = acc + bias.  MODE 1: fused top-4 candidate extraction.
// =====================================================================
template<int NT, int MODE>
__global__ void __launch_bounds__(256, 2)
mma_gemm(int K, int lda, int ldc,
         const float* __restrict__ A, const float* __restrict__ Bimg,
         const float* __restrict__ bias, float* __restrict__ C,
         const float* __restrict__ nrp, const float* __restrict__ enp,
         int* __restrict__ candp) {
    constexpr int NI   = NT / 16;            // 8-wide n tiles per warp
    constexpr int NB   = NT * 32;            // B floats per stage (hi+lo)
    constexpr int ABUF = 4096;               // A floats per buffer (hi+lo)
    extern __shared__ float sm[];
    const int tid = threadIdx.x;
    const int w = tid >> 5, lane = tid & 31;
    const int wm = w & 3, wn = w >> 2;
    const int g = lane >> 2, t = lane & 3;
    const int bx = blockIdx.x, by = blockIdx.y;
    const int KB = K / 16;
    const int chunkp_c = lane ^ ((lane >> 2) & 7);    // consumer chunk perm

    const float* Ab = A + (size_t)by * 128 * lda;
    const uint32_t smBu = smem_u32(sm + 2 * ABUF);

    // producer coords: thread owns rows (m, m+8), one k-quad (rot)
    const int pp = tid >> 2, prot = tid & 3;
    const int pwmi = pp >> 3, pg = pp & 7;
    const int pm = pwmi * 16 + pg;

    float acc[2][NI][4];
    #pragma unroll
    for (int mi = 0; mi < 2; mi++)
        #pragma unroll
        for (int ni = 0; ni < NI; ni++)
            #pragma unroll
            for (int q = 0; q < 4; q++) acc[mi][ni][q] = 0.f;

    float4 ra0, ra1;
    auto gloadA = [&](int st) {
        const int k0 = st * 16 + prot * 4;
        ra0 = *(const float4*)(Ab + (size_t)pm * lda + k0);
        ra1 = *(const float4*)(Ab + (size_t)(pm + 8) * lda + k0);
    };
    auto sstoreA = [&](int abuf) {
        float* AsH = sm + abuf * ABUF;
        float* AsL = AsH + 2048;
        float v0[4] = { ra0.x, ra0.y, ra0.z, ra0.w };
        float v1[4] = { ra1.x, ra1.y, ra1.z, ra1.w };
        #pragma unroll
        for (int c = 0; c < 4; c++) {
            int cc = (c + prot) & 3;
            int k  = prot * 4 + cc;
            int s  = k >> 3, u = (k >> 2) & 1, tt = k & 3;
            int chunk  = pg * 4 + tt;
            int chunkp = chunk ^ pg;                 // ((chunk>>2)&7) == pg
            int widx = ((pwmi * 2 + s) * 32 + chunkp) * 4 + 2 * u;
            float h0 = tf32_rna(v0[cc]), l0 = tf32_rna(v0[cc] - h0);
            float h1 = tf32_rna(v1[cc]), l1 = tf32_rna(v1[cc] - h1);
            *(float2*)(AsH + widx) = make_float2(h0, h1);
            *(float2*)(AsL + widx) = make_float2(l0, l1);
        }
    };
    auto cpB = [&](int st, int bbuf) {
        const float* src = Bimg + ((size_t)bx * KB + st) * NB + tid * (NB / 256);
        uint32_t dst = smBu + (bbuf * NB + tid * (NB / 256)) * 4;
        #pragma unroll
        for (int j = 0; j < NB / 1024; j++) cp16(dst + j * 16, src + j * 4);
    };
    auto compute = [&](int abuf, int bbuf) {
        const float* AsH = sm + abuf * ABUF;
        const float* AsL = AsH + 2048;
        const float* Bs  = sm + 2 * ABUF + bbuf * NB;
        #pragma unroll
        for (int s = 0; s < 2; s++) {
            float4 ah[2], al[2];
            #pragma unroll
            for (int mi = 0; mi < 2; mi++) {
                int q = (((wm * 2 + mi) * 2 + s) * 32 + chunkp_c) * 4;
                ah[mi] = *(const float4*)(AsH + q);
                al[mi] = *(const float4*)(AsL + q);
            }
            uint32_t a0h[4] = { __float_as_uint(ah[0].x), __float_as_uint(ah[0].y),
                                __float_as_uint(ah[0].z), __float_as_uint(ah[0].w) };
            uint32_t a1h[4] = { __float_as_uint(ah[1].x), __float_as_uint(ah[1].y),
                                __float_as_uint(ah[1].z), __float_as_uint(ah[1].w) };
            uint32_t a0l[4] = { __float_as_uint(al[0].x), __float_as_uint(al[0].y),
                                __float_as_uint(al[0].z), __float_as_uint(al[0].w) };
            uint32_t a1l[4] = { __float_as_uint(al[1].x), __float_as_uint(al[1].y),
                                __float_as_uint(al[1].z), __float_as_uint(al[1].w) };
            #pragma unroll
            for (int ni = 0; ni < NI; ni++) {
                int o = (wn * NI + ni) * 256 + s * 128 + lane * 4;
                float4 bv = *(const float4*)(Bs + o);
                uint32_t bhu[2] = { __float_as_uint(bv.x), __float_as_uint(bv.y) };
                uint32_t blu[2] = { __float_as_uint(bv.z), __float_as_uint(bv.w) };
                // per-acc order stays hh -> lh -> hl (bit-identical accumulation)
                mma_tf32(acc[0][ni], a0h, bhu);
                mma_tf32(acc[1][ni], a1h, bhu);
                mma_tf32(acc[0][ni], a0l, bhu);
                mma_tf32(acc[1][ni], a1l, bhu);
                mma_tf32(acc[0][ni], a0h, blu);
                mma_tf32(acc[1][ni], a1h, blu);
            }
        }
    };

    // prologue
    cpB(0, 0); CP_COMMIT();
    if (KB > 1) cpB(1, 1);
    CP_COMMIT();
    gloadA(0);
    sstoreA(0);
    CP_WAIT1();
    __syncthreads();

    for (int st = 0; st < KB; st++) {
        if (st + 1 < KB) gloadA(st + 1);
        compute(st & 1, st % 3);
        if (st + 2 < KB) cpB(st + 2, (st + 2) % 3);
        CP_COMMIT();
        if (st + 1 < KB) sstoreA((st + 1) & 1);
        CP_WAIT1();
        __syncthreads();
    }

    // ---------------- epilogue ----------------
    if (MODE == 0) {
        #pragma unroll
        for (int mi = 0; mi < 2; mi++)
            #pragma unroll
            for (int ni = 0; ni < NI; ni++) {
                int row = by * 128 + wm * 32 + mi * 16 + g;
                int col = bx * NT + wn * (NT / 2) + ni * 8 + 2 * t;
                float b0 = bias[col], b1 = bias[col + 1];
                *(float2*)(C + (size_t)row * ldc + col) =
                    make_float2(acc[mi][ni][0] + b0, acc[mi][ni][1] + b1);
                *(float2*)(C + (size_t)(row + 8) * ldc + col) =
                    make_float2(acc[mi][ni][2] + b0, acc[mi][ni][3] + b1);
            }
    } else {
        __syncthreads();
        float* sd = sm;                       // [2][128][4]
        int*   si = (int*)(sm + 1024);
        #pragma unroll
        for (int mi = 0; mi < 2; mi++)
            #pragma unroll
            for (int h = 0; h < 2; h++) {
                int rloc = wm * 32 + mi * 16 + h * 8 + g;
                float nr = nrp[by * 128 + rloc];
                float d[4] = { 3.4e38f, 3.4e38f, 3.4e38f, 3.4e38f };
                int   ci[4] = { 0, 0, 0, 0 };
                #pragma unroll
                for (int ni = 0; ni < NI; ni++)
                    #pragma unroll
                    for (int cc = 0; cc < 2; cc++) {
                        int cg = bx * NT + wn * (NT / 2) + ni * 8 + 2 * t + cc;
                        float dd = (nr - 2.f * acc[mi][ni][h * 2 + cc]) + enp[cg];
                        ins4(d, ci, dd, cg);
                    }
                #pragma unroll
                for (int o = 1; o < 4; o <<= 1) {
                    float od[4]; int oi[4];
                    #pragma unroll
                    for (int q = 0; q < 4; q++) {
                        od[q] = __shfl_xor_sync(0xffffffffu, d[q], o);
                        oi[q] = __shfl_xor_sync(0xffffffffu, ci[q], o);
                    }
                    #pragma unroll
                    for (int q = 0; q < 4; q++) ins4(d, ci, od[q], oi[q]);
                }
                if (t == 0) {
                    int base = (wn * 128 + rloc) * 4;
                    #pragma unroll
                    for (int q = 0; q < 4; q++) { sd[base + q] = d[q]; si[base + q] = ci[q]; }
                }
            }
        __syncthreads();
        if (tid < 128) {
            float d[4]; int ci[4];
            #pragma unroll
            for (int q = 0; q < 4; q++) { d[q] = sd[tid * 4 + q]; ci[q] = si[tid * 4 + q]; }
            #pragma unroll
            for (int q = 0; q < 4; q++)
                ins4(d, ci, sd[(128 + tid) * 4 + q], si[(128 + tid) * 4 + q]);
            size_t tok = (size_t)by * 128 + tid;
            #pragma unroll
            for (int q = 0; q < 4; q++)
                candp[(size_t)(bx * 4 + q) * BN_TOK + tok] = ci[q];
        }
    }
}

// ---------------- codebook squared norms ----------------
__device__ __forceinline__ float dot256d(const float* a, const float* b) {
    const float4* a4 = (const float4*)a; const float4* b4 = (const float4*)b;
    float s = 0.f;
    #pragma unroll 8
    for (int i = 0; i < 64; i++) {
        float4 x = a4[i], y = b4[i];
        s = fmaf(x.x, y.x, s); s = fmaf(x.y, y.y, s);
        s = fmaf(x.z, y.z, s); s = fmaf(x.w, y.w, s);
    }
    return s;
}
__global__ void norm_kernel(const float* __restrict__ e0, const float* __restrict__ e1,
                            const float* __restrict__ e2) {
    int j = blockIdx.x * blockDim.x + threadIdx.x;
    if (j >= 448) return;
    const float* r;
    if (j < KC0)            r = e0 + j * PDIM;
    else if (j < KC0 + KC1) r = e1 + (j - KC0) * PDIM;
    else                    r = e2 + (j - KC0 - KC1) * PDIM;
    g_enorm[j] = dot256d(r, r);
}

// ---------------- per-token ||z_proj||^2 ----------------
__global__ void rownorm_kernel() {
    int tk = blockIdx.x * 8 + (threadIdx.x >> 5);
    int lane = threadIdx.x & 31;
    const float4* row = (const float4*)(g_zproj + (size_t)tk * PDIM);
    float s = 0.f;
    #pragma unroll
    for (int i = lane; i < 64; i += 32) {
        float4 v = row[i];
        s = fmaf(v.x, v.x, s); s = fmaf(v.y, v.y, s);
        s = fmaf(v.z, v.z, s); s = fmaf(v.w, v.w, s);
    }
    #pragma unroll
    for (int o = 16; o; o >>= 1) s += __shfl_down_sync(0xffffffffu, s, o);
    if (lane == 0) g_nr[tk] = s;
}

// ---------------- refine: exact fp32 re-rank of candidates + residual update
// MODE 0: Rout = g_R, loss init.  1: in-place.  2: qcomb = zproj - r_new.
template<int NC, int MODE>
__global__ void refine_kernel(const float* __restrict__ Rin, float* __restrict__ Rout,
                              const float* __restrict__ emb, int enoff, int level,
                              const int* __restrict__ candp, float* __restrict__ out) {
    const int warp = threadIdx.x >> 5, lane = threadIdx.x & 31;
    const int tk = blockIdx.x * 8 + warp;
    const float4* r4 = (const float4*)(Rin + (size_t)tk * PDIM);
    float4 ra = r4[lane * 2], rb = r4[lane * 2 + 1];
    float bestd = 3.4e38f; int bestc = 0x7fffffff;
    #pragma unroll
    for (int j = 0; j < NC; j++) {
        const int cj = candp[(size_t)j * BN_TOK + tk];
        const float4* e4 = (const float4*)(emb + (size_t)cj * PDIM);
        float4 ea = e4[lane * 2], eb = e4[lane * 2 + 1];
        float s = 0.f;
        s = fmaf(ra.x, ea.x, s); s = fmaf(ra.y, ea.y, s);
        s = fmaf(ra.z, ea.z, s); s = fmaf(ra.w, ea.w, s);
        s = fmaf(rb.x, eb.x, s); s = fmaf(rb.y, eb.y, s);
        s = fmaf(rb.z, eb.z, s); s = fmaf(rb.w, eb.w, s);
        #pragma unroll
        for (int o = 16; o; o >>= 1) s += __shfl_xor_sync(0xffffffffu, s, o);
        float d = __fadd_rn(g_enorm[enoff + cj], __fmul_rn(-2.f, s));
        if (d < bestd || (d == bestd && cj < bestc)) { bestd = d; bestc = cj; }
    }
    const float4* e4 = (const float4*)(emb + (size_t)bestc * PDIM);
    float4 ea = e4[lane * 2], eb = e4[lane * 2 + 1];
    float4 na, nb;
    na.x = ra.x - ea.x; na.y = ra.y - ea.y; na.z = ra.z - ea.z; na.w = ra.w - ea.w;
    nb.x = rb.x - eb.x; nb.y = rb.y - eb.y; nb.z = rb.z - eb.z; nb.w = rb.w - eb.w;
    float ns = 0.f;
    ns = fmaf(na.x, na.x, ns); ns = fmaf(na.y, na.y, ns);
    ns = fmaf(na.z, na.z, ns); ns = fmaf(na.w, na.w, ns);
    ns = fmaf(nb.x, nb.x, ns); ns = fmaf(nb.y, nb.y, ns);
    ns = fmaf(nb.z, nb.z, ns); ns = fmaf(nb.w, nb.w, ns);
    #pragma unroll
    for (int o = 16; o; o >>= 1) ns += __shfl_xor_sync(0xffffffffu, ns, o);

    if (MODE != 2) {
        float4* ro = (float4*)(Rout + (size_t)tk * PDIM);
        ro[lane * 2] = na; ro[lane * 2 + 1] = nb;
    } else {
        const float4* z4 = (const float4*)(g_zproj + (size_t)tk * PDIM);
        float4 za = z4[lane * 2], zb = z4[lane * 2 + 1];
        float4 qa, qb;
        qa.x = za.x - na.x; qa.y = za.y - na.y; qa.z = za.z - na.z; qa.w = za.w - na.w;
        qb.x = zb.x - nb.x; qb.y = zb.y - nb.y; qb.z = zb.z - nb.z; qb.w = zb.w - nb.w;
        float4* qo = (float4*)(g_qcomb + (size_t)tk * PDIM);
        qo[lane * 2] = qa; qo[lane * 2 + 1] = qb;
    }
    if (lane == 0) {
        g_nr[tk] = ns;
        if (MODE == 0) g_dmin[tk] = ns; else g_dmin[tk] += ns;
        out[OUT_IDX + level * BN_TOK + tk] = (float)bestc;
    }
}

// ---------------- loss finalize ----------------
__global__ void loss_final(float* __restrict__ out) {
    __shared__ float red[256];
    const int p = threadIdx.x;
    float s = 0.f;
    for (int i = p; i < BN_TOK; i += 256) s += g_dmin[i];
    red[p] = s;
    __syncthreads();
    for (int st = 128; st; st >>= 1) {
        if (p < st) red[p] += red[p + st];
        __syncthreads();
    }
    if (p == 0)
        out[OUT_LOSS] = 0.25f * red[0] / ((float)BN_TOK * (float)PDIM * 3.f);
}

// ---------------- launcher ----------------
extern "C" void kernel_launch(void* const* d_in, const int* in_sizes, int n_in,
                              void* d_out, int out_size) {
    const float* z     = (const float*)d_in[0];
    const float* W_in  = (const float*)d_in[1];
    const float* b_in  = (const float*)d_in[2];
    const float* W_out = (const float*)d_in[3];
    const float* b_out = (const float*)d_in[4];
    const float* e0    = (const float*)d_in[5];
    const float* e1    = (const float*)d_in[6];
    const float* e2    = (const float*)d_in[7];
    float* out = (float*)d_out;

    float *zproj, *R, *qcomb, *nr, *enorm;
    float *bwin, *bwout, *be0, *be1, *be2;
    int *cand;
    cudaGetSymbolAddress((void**)&zproj, g_zproj);
    cudaGetSymbolAddress((void**)&R,     g_R);
    cudaGetSymbolAddress((void**)&qcomb, g_qcomb);
    cudaGetSymbolAddress((void**)&nr,    g_nr);
    cudaGetSymbolAddress((void**)&enorm, g_enorm);
    cudaGetSymbolAddress((void**)&cand,  g_cand);
    cudaGetSymbolAddress((void**)&bwin,  g_BWin);
    cudaGetSymbolAddress((void**)&bwout, g_BWout);
    cudaGetSymbolAddress((void**)&be0,   g_Be0);
    cudaGetSymbolAddress((void**)&be1,   g_Be1);
    cudaGetSymbolAddress((void**)&be2,   g_Be2);

    const int SM128 = (2 * 4096 + 3 * 128 * 32) * 4;   // 32KB A + 48KB B = 81920
    const int SM64  = (2 * 4096 + 3 * 64 * 32) * 4;    // 32KB A + 24KB B = 57344
    cudaFuncSetAttribute(mma_gemm<128, 0>, cudaFuncAttributeMaxDynamicSharedMemorySize, SM128);
    cudaFuncSetAttribute(mma_gemm<128, 1>, cudaFuncAttributeMaxDynamicSharedMemorySize, SM128);
    cudaFuncSetAttribute(mma_gemm<64, 1>,  cudaFuncAttributeMaxDynamicSharedMemorySize, SM64);

    // operand prep (B images) + codebook norms
    bprep<128><<<(256 * 1408 + 255) / 256, 256>>>(W_in,  bwin,  1408, 256,  1, 256 * 1408);
    bprep<128><<<(1408 * 256 + 255) / 256, 256>>>(W_out, bwout, 256,  1408, 1, 1408 * 256);
    bprep<64> <<<(64 * 256 + 255) / 256,   256>>>(e0,    be0,   256,  256,  0, 64 * 256);
    bprep<128><<<(128 * 256 + 255) / 256,  256>>>(e1,    be1,   256,  256,  0, 128 * 256);
    bprep<128><<<(256 * 256 + 255) / 256,  256>>>(e2,    be2,   256,  256,  0, 256 * 256);
    norm_kernel<<<2, 256>>>(e0, e1, e2);

    // z_proj = z @ W_in + b_in     [32768,1408] x [1408,256]
    mma_gemm<128, 0><<<dim3(2, BN_TOK / 128), 256, SM128>>>(
        DDIM, DDIM, PDIM, z, bwin, b_in, zproj, nullptr, nullptr, nullptr);
    rownorm_kernel<<<BN_TOK / 8, 256>>>();

    // level 0 (64 codes) -> 4 candidates
    mma_gemm<64, 1><<<dim3(1, BN_TOK / 128), 256, SM64>>>(
        PDIM, PDIM, 0, zproj, be0, nullptr, nullptr, nr, enorm, cand);
    refine_kernel<4, 0><<<BN_TOK / 8, 256>>>(zproj, R, e0, 0, 0, cand, out);

    // level 1 (128 codes) -> 4 candidates
    mma_gemm<128, 1><<<dim3(1, BN_TOK / 128), 256, SM128>>>(
        PDIM, PDIM, 0, R, be1, nullptr, nullptr, nr, enorm + KC0, cand);
    refine_kernel<4, 1><<<BN_TOK / 8, 256>>>(R, R, e1, KC0, 1, cand, out);

    // level 2 (256 codes; two N-blocks) -> 8 candidates
    mma_gemm<128, 1><<<dim3(2, BN_TOK / 128), 256, SM128>>>(
        PDIM, PDIM, 0, R, be2, nullptr, nullptr, nr, enorm + KC0 + KC1, cand);
    refine_kernel<8, 2><<<BN_TOK / 8, 256>>>(R, nullptr, e2, KC0 + KC1, 2, cand, out);

    loss_final<<<1, 256>>>(out);

    // z_q_out = qcomb @ W_out + b_out   [32768,256] x [256,1408]
    mma_gemm<128, 0><<<dim3(11, BN_TOK / 128), 256, SM128>>>(
        PDIM, PDIM, DDIM, qcomb, bwout, b_out, out, nullptr, nullptr, nullptr);
}

// round 11
// speedup vs baseline: 1.4102x; 1.4102x over previous
#include <cuda_runtime.h>
#include <cstdint>

// ---------------- problem constants ----------------
#define BN_TOK 32768
#define DDIM   1408
#define PDIM   256
#define KC0    64
#define KC1    128
#define KC2    256
#define OUT_IDX  46137344
#define OUT_LOSS 46235648

// ---------------- device scratch ----------------
__device__ float g_zproj[BN_TOK * PDIM];
__device__ float g_R    [BN_TOK * PDIM];
__device__ float g_nr   [BN_TOK];
__device__ float g_dmin [BN_TOK];
__device__ float g_enorm[512];
__device__ int   g_cand [8 * BN_TOK];
__device__ int   g_idx  [3 * BN_TOK];
__device__ float g_ecat [512 * PDIM];      // concat codebooks, zero-padded to 512
__device__ float g_EW   [512 * DDIM];      // ecat @ W_out  (rows 448+ unused)
// pre-split (hi/lo tf32) fragment-ordered B operand images
__device__ float g_BWin [720896];   // N=256,  K=1408, NT=128
__device__ float g_BWout[720896];   // N=1408, K=256,  NT=128
__device__ float g_Be0  [32768];    // N=64,   K=256,  NT=64
__device__ float g_Be1  [65536];    // N=128,  K=256,  NT=128
__device__ float g_Be2  [131072];   // N=256,  K=256,  NT=128

// ---------------- helpers ----------------
__device__ __forceinline__ float tf32_rna(float x) {
    uint32_t u; asm("cvt.rna.tf32.f32 %0, %1;" : "=r"(u) : "f"(x));
    return __uint_as_float(u);
}
__device__ __forceinline__ void mma_tf32(float* c, const uint32_t* a, const uint32_t* b) {
    asm volatile("mma.sync.aligned.m16n8k8.row.col.f32.tf32.tf32.f32 "
        "{%0,%1,%2,%3}, {%4,%5,%6,%7}, {%8,%9}, {%0,%1,%2,%3};"
        : "+f"(c[0]), "+f"(c[1]), "+f"(c[2]), "+f"(c[3])
        : "r"(a[0]), "r"(a[1]), "r"(a[2]), "r"(a[3]), "r"(b[0]), "r"(b[1]));
}
__device__ __forceinline__ uint32_t smem_u32(const void* p) {
    uint32_t a;
    asm("{ .reg .u64 t; cvta.to.shared.u64 t, %1; cvt.u32.u64 %0, t; }" : "=r"(a) : "l"(p));
    return a;
}
__device__ __forceinline__ void cp16(uint32_t dst, const void* src) {
    asm volatile("cp.async.ca.shared.global [%0], [%1], 16;" :: "r"(dst), "l"(src));
}
#define CP_COMMIT() asm volatile("cp.async.commit_group;" ::: "memory")
#define CP_WAIT1()  asm volatile("cp.async.wait_group 1;" ::: "memory")

// insert (dv, cg) into sorted top-4 list (ascending d, index tie-break)
__device__ __forceinline__ void ins4(float* d, int* ci, float dv, int cg) {
    #pragma unroll
    for (int q = 0; q < 4; q++) {
        bool better = dv < d[q] || (dv == d[q] && cg < ci[q]);
        float td = d[q]; int ti = ci[q];
        if (better) { d[q] = dv; ci[q] = cg; dv = td; cg = ti; }
    }
}

// ---------------- B image prep (round-10 packed layout, proven) ----------
template<int NT>
__global__ void bprep(const float* __restrict__ src, float* __restrict__ img,
                      int K, int ld, int trans, int total) {
    int i = blockIdx.x * 256 + threadIdx.x;
    if (i >= total) return;
    constexpr int NI = NT / 16;
    int word = i & (NT * 16 - 1);
    int rest = i / (NT * 16);
    int kb = rest % (K / 16);
    int nb = rest / (K / 16);
    int w = word & 1;
    int t = (word >> 1) & 3;
    int g = (word >> 3) & 7;
    int s = (word >> 6) & 1;
    int tl = word >> 7;
    int wn = tl / NI, ni = tl % NI;
    int n = nb * NT + wn * (NT / 2) + ni * 8 + g;
    int k = kb * 16 + s * 8 + t + w * 4;
    float x = trans ? src[(size_t)k * ld + n] : src[(size_t)n * ld + k];
    float hi = tf32_rna(x), lo = tf32_rna(x - hi);
    size_t base = (size_t)rest * (NT * 32);
    int lane = g * 4 + t;
    int off = tl * 256 + s * 128 + lane * 4 + w;
    img[base + off]     = hi;
    img[base + off + 2] = lo;
}

// ---------------- concat codebooks into [512 x 256], zero-padded ----------
__global__ void ecat_kernel(const float* __restrict__ e0, const float* __restrict__ e1,
                            const float* __restrict__ e2) {
    int i = blockIdx.x * 256 + threadIdx.x;     // over 512*256
    int row = i >> 8, col = i & 255;
    float v = 0.f;
    if (row < 64)        v = e0[row * 256 + col];
    else if (row < 192)  v = e1[(row - 64) * 256 + col];
    else if (row < 448)  v = e2[(row - 192) * 256 + col];
    g_ecat[i] = v;
}

// =====================================================================
// tf32 3-product warp-MMA GEMM (round-10, proven).  CTA tile 128m x NT.
// MODE 0: C = acc (+ bias if non-null).  MODE 1: top-4 candidate extract.
// =====================================================================
template<int NT, int MODE>
__global__ void __launch_bounds__(256, 2)
mma_gemm(int K, int lda, int ldc,
         const float* __restrict__ A, const float* __restrict__ Bimg,
         const float* __restrict__ bias, float* __restrict__ C,
         const float* __restrict__ nrp, const float* __restrict__ enp,
         int* __restrict__ candp) {
    constexpr int NI   = NT / 16;
    constexpr int NB   = NT * 32;
    constexpr int ABUF = 4096;
    extern __shared__ float sm[];
    const int tid = threadIdx.x;
    const int w = tid >> 5, lane = tid & 31;
    const int wm = w & 3, wn = w >> 2;
    const int g = lane >> 2, t = lane & 3;
    const int bx = blockIdx.x, by = blockIdx.y;
    const int KB = K / 16;
    const int chunkp_c = lane ^ ((lane >> 2) & 7);

    const float* Ab = A + (size_t)by * 128 * lda;
    const uint32_t smBu = smem_u32(sm + 2 * ABUF);

    const int pp = tid >> 2, prot = tid & 3;
    const int pwmi = pp >> 3, pg = pp & 7;
    const int pm = pwmi * 16 + pg;

    float acc[2][NI][4];
    #pragma unroll
    for (int mi = 0; mi < 2; mi++)
        #pragma unroll
        for (int ni = 0; ni < NI; ni++)
            #pragma unroll
            for (int q = 0; q < 4; q++) acc[mi][ni][q] = 0.f;

    float4 ra0, ra1;
    auto gloadA = [&](int st) {
        const int k0 = st * 16 + prot * 4;
        ra0 = *(const float4*)(Ab + (size_t)pm * lda + k0);
        ra1 = *(const float4*)(Ab + (size_t)(pm + 8) * lda + k0);
    };
    auto sstoreA = [&](int abuf) {
        float* AsH = sm + abuf * ABUF;
        float* AsL = AsH + 2048;
        float v0[4] = { ra0.x, ra0.y, ra0.z, ra0.w };
        float v1[4] = { ra1.x, ra1.y, ra1.z, ra1.w };
        #pragma unroll
        for (int c = 0; c < 4; c++) {
            int cc = (c + prot) & 3;
            int k  = prot * 4 + cc;
            int s  = k >> 3, u = (k >> 2) & 1, tt = k & 3;
            int chunk  = pg * 4 + tt;
            int chunkp = chunk ^ pg;
            int widx = ((pwmi * 2 + s) * 32 + chunkp) * 4 + 2 * u;
            float h0 = tf32_rna(v0[cc]), l0 = tf32_rna(v0[cc] - h0);
            float h1 = tf32_rna(v1[cc]), l1 = tf32_rna(v1[cc] - h1);
            *(float2*)(AsH + widx) = make_float2(h0, h1);
            *(float2*)(AsL + widx) = make_float2(l0, l1);
        }
    };
    auto cpB = [&](int st, int bbuf) {
        const float* src = Bimg + ((size_t)bx * KB + st) * NB + tid * (NB / 256);
        uint32_t dst = smBu + (bbuf * NB + tid * (NB / 256)) * 4;
        #pragma unroll
        for (int j = 0; j < NB / 1024; j++) cp16(dst + j * 16, src + j * 4);
    };
    auto compute = [&](int abuf, int bbuf) {
        const float* AsH = sm + abuf * ABUF;
        const float* AsL = AsH + 2048;
        const float* Bs  = sm + 2 * ABUF + bbuf * NB;
        #pragma unroll
        for (int s = 0; s < 2; s++) {
            float4 ah[2], al[2];
            #pragma unroll
            for (int mi = 0; mi < 2; mi++) {
                int q = (((wm * 2 + mi) * 2 + s) * 32 + chunkp_c) * 4;
                ah[mi] = *(const float4*)(AsH + q);
                al[mi] = *(const float4*)(AsL + q);
            }
            uint32_t a0h[4] = { __float_as_uint(ah[0].x), __float_as_uint(ah[0].y),
                                __float_as_uint(ah[0].z), __float_as_uint(ah[0].w) };
            uint32_t a1h[4] = { __float_as_uint(ah[1].x), __float_as_uint(ah[1].y),
                                __float_as_uint(ah[1].z), __float_as_uint(ah[1].w) };
            uint32_t a0l[4] = { __float_as_uint(al[0].x), __float_as_uint(al[0].y),
                                __float_as_uint(al[0].z), __float_as_uint(al[0].w) };
            uint32_t a1l[4] = { __float_as_uint(al[1].x), __float_as_uint(al[1].y),
                                __float_as_uint(al[1].z), __float_as_uint(al[1].w) };
            #pragma unroll
            for (int ni = 0; ni < NI; ni++) {
                int o = (wn * NI + ni) * 256 + s * 128 + lane * 4;
                float4 bv = *(const float4*)(Bs + o);
                uint32_t bhu[2] = { __float_as_uint(bv.x), __float_as_uint(bv.y) };
                uint32_t blu[2] = { __float_as_uint(bv.z), __float_as_uint(bv.w) };
                mma_tf32(acc[0][ni], a0h, bhu);
                mma_tf32(acc[1][ni], a1h, bhu);
                mma_tf32(acc[0][ni], a0l, bhu);
                mma_tf32(acc[1][ni], a1l, bhu);
                mma_tf32(acc[0][ni], a0h, blu);
                mma_tf32(acc[1][ni], a1h, blu);
            }
        }
    };

    // prologue
    cpB(0, 0); CP_COMMIT();
    if (KB > 1) cpB(1, 1);
    CP_COMMIT();
    gloadA(0);
    sstoreA(0);
    CP_WAIT1();
    __syncthreads();

    for (int st = 0; st < KB; st++) {
        if (st + 1 < KB) gloadA(st + 1);
        compute(st & 1, st % 3);
        if (st + 2 < KB) cpB(st + 2, (st + 2) % 3);
        CP_COMMIT();
        if (st + 1 < KB) sstoreA((st + 1) & 1);
        CP_WAIT1();
        __syncthreads();
    }

    // ---------------- epilogue ----------------
    if (MODE == 0) {
        #pragma unroll
        for (int mi = 0; mi < 2; mi++)
            #pragma unroll
            for (int ni = 0; ni < NI; ni++) {
                int row = by * 128 + wm * 32 + mi * 16 + g;
                int col = bx * NT + wn * (NT / 2) + ni * 8 + 2 * t;
                float b0 = bias ? bias[col]     : 0.f;
                float b1 = bias ? bias[col + 1] : 0.f;
                *(float2*)(C + (size_t)row * ldc + col) =
                    make_float2(acc[mi][ni][0] + b0, acc[mi][ni][1] + b1);
                *(float2*)(C + (size_t)(row + 8) * ldc + col) =
                    make_float2(acc[mi][ni][2] + b0, acc[mi][ni][3] + b1);
            }
    } else {
        __syncthreads();
        float* sd = sm;                       // [2][128][4]
        int*   si = (int*)(sm + 1024);
        #pragma unroll
        for (int mi = 0; mi < 2; mi++)
            #pragma unroll
            for (int h = 0; h < 2; h++) {
                int rloc = wm * 32 + mi * 16 + h * 8 + g;
                float nr = nrp[by * 128 + rloc];
                float d[4] = { 3.4e38f, 3.4e38f, 3.4e38f, 3.4e38f };
                int   ci[4] = { 0, 0, 0, 0 };
                #pragma unroll
                for (int ni = 0; ni < NI; ni++)
                    #pragma unroll
                    for (int cc = 0; cc < 2; cc++) {
                        int cg = bx * NT + wn * (NT / 2) + ni * 8 + 2 * t + cc;
                        float dd = (nr - 2.f * acc[mi][ni][h * 2 + cc]) + enp[cg];
                        ins4(d, ci, dd, cg);
                    }
                #pragma unroll
                for (int o = 1; o < 4; o <<= 1) {
                    float od[4]; int oi[4];
                    #pragma unroll
                    for (int q = 0; q < 4; q++) {
                        od[q] = __shfl_xor_sync(0xffffffffu, d[q], o);
                        oi[q] = __shfl_xor_sync(0xffffffffu, ci[q], o);
                    }
                    #pragma unroll
                    for (int q = 0; q < 4; q++) ins4(d, ci, od[q], oi[q]);
                }
                if (t == 0) {
                    int base = (wn * 128 + rloc) * 4;
                    #pragma unroll
                    for (int q = 0; q < 4; q++) { sd[base + q] = d[q]; si[base + q] = ci[q]; }
                }
            }
        __syncthreads();
        if (tid < 128) {
            float d[4]; int ci[4];
            #pragma unroll
            for (int q = 0; q < 4; q++) { d[q] = sd[tid * 4 + q]; ci[q] = si[tid * 4 + q]; }
            #pragma unroll
            for (int q = 0; q < 4; q++)
                ins4(d, ci, sd[(128 + tid) * 4 + q], si[(128 + tid) * 4 + q]);
            size_t tok = (size_t)by * 128 + tid;
            #pragma unroll
            for (int q = 0; q < 4; q++)
                candp[(size_t)(bx * 4 + q) * BN_TOK + tok] = ci[q];
        }
    }
}

// ---------------- codebook squared norms ----------------
__device__ __forceinline__ float dot256d(const float* a, const float* b) {
    const float4* a4 = (const float4*)a; const float4* b4 = (const float4*)b;
    float s = 0.f;
    #pragma unroll 8
    for (int i = 0; i < 64; i++) {
        float4 x = a4[i], y = b4[i];
        s = fmaf(x.x, y.x, s); s = fmaf(x.y, y.y, s);
        s = fmaf(x.z, y.z, s); s = fmaf(x.w, y.w, s);
    }
    return s;
}
__global__ void norm_kernel(const float* __restrict__ e0, const float* __restrict__ e1,
                            const float* __restrict__ e2) {
    int j = blockIdx.x * blockDim.x + threadIdx.x;
    if (j >= 448) return;
    const float* r;
    if (j < KC0)            r = e0 + j * PDIM;
    else if (j < KC0 + KC1) r = e1 + (j - KC0) * PDIM;
    else                    r = e2 + (j - KC0 - KC1) * PDIM;
    g_enorm[j] = dot256d(r, r);
}

// ---------------- per-token ||z_proj||^2 ----------------
__global__ void rownorm_kernel() {
    int tk = blockIdx.x * 8 + (threadIdx.x >> 5);
    int lane = threadIdx.x & 31;
    const float4* row = (const float4*)(g_zproj + (size_t)tk * PDIM);
    float s = 0.f;
    #pragma unroll
    for (int i = lane; i < 64; i += 32) {
        float4 v = row[i];
        s = fmaf(v.x, v.x, s); s = fmaf(v.y, v.y, s);
        s = fmaf(v.z, v.z, s); s = fmaf(v.w, v.w, s);
    }
    #pragma unroll
    for (int o = 16; o; o >>= 1) s += __shfl_down_sync(0xffffffffu, s, o);
    if (lane == 0) g_nr[tk] = s;
}

// ---------------- refine: exact fp32 re-rank of candidates + residual update
// MODE 0: Rout = g_R, loss init.  1: in-place.  2: indices/loss only.
template<int NC, int MODE>
__global__ void refine_kernel(const float* __restrict__ Rin, float* __restrict__ Rout,
                              const float* __restrict__ emb, int enoff, int level,
                              const int* __restrict__ candp, float* __restrict__ out) {
    const int warp = threadIdx.x >> 5, lane = threadIdx.x & 31;
    const int tk = blockIdx.x * 8 + warp;
    const float4* r4 = (const float4*)(Rin + (size_t)tk * PDIM);
    float4 ra = r4[lane * 2], rb = r4[lane * 2 + 1];
    float bestd = 3.4e38f; int bestc = 0x7fffffff;
    #pragma unroll
    for (int j = 0; j < NC; j++) {
        const int cj = candp[(size_t)j * BN_TOK + tk];
        const float4* e4 = (const float4*)(emb + (size_t)cj * PDIM);
        float4 ea = e4[lane * 2], eb = e4[lane * 2 + 1];
        float s = 0.f;
        s = fmaf(ra.x, ea.x, s); s = fmaf(ra.y, ea.y, s);
        s = fmaf(ra.z, ea.z, s); s = fmaf(ra.w, ea.w, s);
        s = fmaf(rb.x, eb.x, s); s = fmaf(rb.y, eb.y, s);
        s = fmaf(rb.z, eb.z, s); s = fmaf(rb.w, eb.w, s);
        #pragma unroll
        for (int o = 16; o; o >>= 1) s += __shfl_xor_sync(0xffffffffu, s, o);
        float d = __fadd_rn(g_enorm[enoff + cj], __fmul_rn(-2.f, s));
        if (d < bestd || (d == bestd && cj < bestc)) { bestd = d; bestc = cj; }
    }
    const float4* e4 = (const float4*)(emb + (size_t)bestc * PDIM);
    float4 ea = e4[lane * 2], eb = e4[lane * 2 + 1];
    float4 na, nb;
    na.x = ra.x - ea.x; na.y = ra.y - ea.y; na.z = ra.z - ea.z; na.w = ra.w - ea.w;
    nb.x = rb.x - eb.x; nb.y = rb.y - eb.y; nb.z = rb.z - eb.z; nb.w = rb.w - eb.w;
    float ns = 0.f;
    ns = fmaf(na.x, na.x, ns); ns = fmaf(na.y, na.y, ns);
    ns = fmaf(na.z, na.z, ns); ns = fmaf(na.w, na.w, ns);
    ns = fmaf(nb.x, nb.x, ns); ns = fmaf(nb.y, nb.y, ns);
    ns = fmaf(nb.z, nb.z, ns); ns = fmaf(nb.w, nb.w, ns);
    #pragma unroll
    for (int o = 16; o; o >>= 1) ns += __shfl_xor_sync(0xffffffffu, ns, o);

    if (MODE != 2) {
        float4* ro = (float4*)(Rout + (size_t)tk * PDIM);
        ro[lane * 2] = na; ro[lane * 2 + 1] = nb;
    }
    if (lane == 0) {
        g_nr[tk] = ns;
        if (MODE == 0) g_dmin[tk] = ns; else g_dmin[tk] += ns;
        g_idx[level * BN_TOK + tk] = bestc;
        out[OUT_IDX + level * BN_TOK + tk] = (float)bestc;
    }
}

// ---------------- output gather-add: out[t] = EW[i0]+EW[64+i1]+EW[192+i2]+b
__global__ void gather_out(const float* __restrict__ bias, float* __restrict__ out) {
    const int tk = blockIdx.x;
    const int j  = threadIdx.x;                         // 0..351 (float4 index)
    const int i0 = g_idx[tk], i1 = g_idx[BN_TOK + tk], i2 = g_idx[2 * BN_TOK + tk];
    const float4* r0 = (const float4*)(g_EW + (size_t)i0 * DDIM);
    const float4* r1 = (const float4*)(g_EW + (size_t)(64 + i1) * DDIM);
    const float4* r2 = (const float4*)(g_EW + (size_t)(192 + i2) * DDIM);
    float4 a = r0[j], b = r1[j], c = r2[j];
    float4 bb = ((const float4*)bias)[j];
    float4 v;
    v.x = a.x + b.x + c.x + bb.x;
    v.y = a.y + b.y + c.y + bb.y;
    v.z = a.z + b.z + c.z + bb.z;
    v.w = a.w + b.w + c.w + bb.w;
    ((float4*)(out + (size_t)tk * DDIM))[j] = v;
}

// ---------------- loss finalize ----------------
__global__ void loss_final(float* __restrict__ out) {
    __shared__ float red[256];
    const int p = threadIdx.x;
    float s = 0.f;
    for (int i = p; i < BN_TOK; i += 256) s += g_dmin[i];
    red[p] = s;
    __syncthreads();
    for (int st = 128; st; st >>= 1) {
        if (p < st) red[p] += red[p + st];
        __syncthreads();
    }
    if (p == 0)
        out[OUT_LOSS] = 0.25f * red[0] / ((float)BN_TOK * (float)PDIM * 3.f);
}

// ---------------- launcher ----------------
extern "C" void kernel_launch(void* const* d_in, const int* in_sizes, int n_in,
                              void* d_out, int out_size) {
    const float* z     = (const float*)d_in[0];
    const float* W_in  = (const float*)d_in[1];
    const float* b_in  = (const float*)d_in[2];
    const float* W_out = (const float*)d_in[3];
    const float* b_out = (const float*)d_in[4];
    const float* e0    = (const float*)d_in[5];
    const float* e1    = (const float*)d_in[6];
    const float* e2    = (const float*)d_in[7];
    float* out = (float*)d_out;

    float *zproj, *R, *nr, *enorm, *ecat, *ew;
    float *bwin, *bwout, *be0, *be1, *be2;
    int *cand;
    cudaGetSymbolAddress((void**)&zproj, g_zproj);
    cudaGetSymbolAddress((void**)&R,     g_R);
    cudaGetSymbolAddress((void**)&nr,    g_nr);
    cudaGetSymbolAddress((void**)&enorm, g_enorm);
    cudaGetSymbolAddress((void**)&cand,  g_cand);
    cudaGetSymbolAddress((void**)&ecat,  g_ecat);
    cudaGetSymbolAddress((void**)&ew,    g_EW);
    cudaGetSymbolAddress((void**)&bwin,  g_BWin);
    cudaGetSymbolAddress((void**)&bwout, g_BWout);
    cudaGetSymbolAddress((void**)&be0,   g_Be0);
    cudaGetSymbolAddress((void**)&be1,   g_Be1);
    cudaGetSymbolAddress((void**)&be2,   g_Be2);

    const int SM128 = (2 * 4096 + 3 * 128 * 32) * 4;   // 81920
    const int SM64  = (2 * 4096 + 3 * 64 * 32) * 4;    // 57344
    cudaFuncSetAttribute(mma_gemm<128, 0>, cudaFuncAttributeMaxDynamicSharedMemorySize, SM128);
    cudaFuncSetAttribute(mma_gemm<128, 1>, cudaFuncAttributeMaxDynamicSharedMemorySize, SM128);
    cudaFuncSetAttribute(mma_gemm<64, 1>,  cudaFuncAttributeMaxDynamicSharedMemorySize, SM64);

    // operand prep (B images) + concat codebooks + norms
    bprep<128><<<(256 * 1408 + 255) / 256, 256>>>(W_in,  bwin,  1408, 256,  1, 256 * 1408);
    bprep<128><<<(1408 * 256 + 255) / 256, 256>>>(W_out, bwout, 256,  1408, 1, 1408 * 256);
    bprep<64> <<<(64 * 256 + 255) / 256,   256>>>(e0,    be0,   256,  256,  0, 64 * 256);
    bprep<128><<<(128 * 256 + 255) / 256,  256>>>(e1,    be1,   256,  256,  0, 128 * 256);
    bprep<128><<<(256 * 256 + 255) / 256,  256>>>(e2,    be2,   256,  256,  0, 256 * 256);
    ecat_kernel<<<512, 256>>>(e0, e1, e2);
    norm_kernel<<<2, 256>>>(e0, e1, e2);

    // EW = ecat @ W_out     [512,256] x [256,1408]   (no bias)
    mma_gemm<128, 0><<<dim3(11, 4), 256, SM128>>>(
        PDIM, PDIM, DDIM, ecat, bwout, nullptr, ew, nullptr, nullptr, nullptr);

    // z_proj = z @ W_in + b_in     [32768,1408] x [1408,256]
    mma_gemm<128, 0><<<dim3(2, BN_TOK / 128), 256, SM128>>>(
        DDIM, DDIM, PDIM, z, bwin, b_in, zproj, nullptr, nullptr, nullptr);
    rownorm_kernel<<<BN_TOK / 8, 256>>>();

    // level 0 (64 codes) -> 4 candidates
    mma_gemm<64, 1><<<dim3(1, BN_TOK / 128), 256, SM64>>>(
        PDIM, PDIM, 0, zproj, be0, nullptr, nullptr, nr, enorm, cand);
    refine_kernel<4, 0><<<BN_TOK / 8, 256>>>(zproj, R, e0, 0, 0, cand, out);

    // level 1 (128 codes) -> 4 candidates
    mma_gemm<128, 1><<<dim3(1, BN_TOK / 128), 256, SM128>>>(
        PDIM, PDIM, 0, R, be1, nullptr, nullptr, nr, enorm + KC0, cand);
    refine_kernel<4, 1><<<BN_TOK / 8, 256>>>(R, R, e1, KC0, 1, cand, out);

    // level 2 (256 codes; two N-blocks) -> 8 candidates
    mma_gemm<128, 1><<<dim3(2, BN_TOK / 128), 256, SM128>>>(
        PDIM, PDIM, 0, R, be2, nullptr, nullptr, nr, enorm + KC0 + KC1, cand);
    refine_kernel<8, 2><<<BN_TOK / 8, 256>>>(R, nullptr, e2, KC0 + KC1, 2, cand, out);

    loss_final<<<1, 256>>>(out);

    // z_q_out via gather-add of precomputed EW rows
    gather_out<<<BN_TOK, 352>>>(b_out, out);
}

// round 16
// speedup vs baseline: 1.5402x; 1.0922x over previous
#include <cuda_runtime.h>
#include <cuda_fp16.h>
#include <cstdint>

// ---------------- problem constants ----------------
#define BN_TOK 32768
#define DDIM   1408
#define PDIM   256
#define KC0    64
#define KC1    128
#define KC2    256
#define OUT_IDX  46137344
#define OUT_LOSS 46235648

// ---------------- device scratch ----------------
__device__ float g_zproj[BN_TOK * PDIM];
__device__ float g_R    [BN_TOK * PDIM];
__device__ float g_nr   [BN_TOK];
__device__ float g_dmin [BN_TOK];
__device__ float g_enorm[512];
__device__ int   g_cand [8 * BN_TOK];
__device__ int   g_idx  [3 * BN_TOK];
__device__ float g_ecat [512 * PDIM];
__device__ float g_EW   [512 * DDIM];
// tf32 (hi/lo) packed image for W_in (z_proj path — round-11 proven)
__device__ float g_BWin [720896];   // N=256,  K=1408, NT=128
// fp16 (hi/lo) packed images for W_out + codebooks
__device__ float g_BWout[360448];   // N=1408, K=256,  NT=128
__device__ float g_Be0  [16384];    // N=64,   K=256,  NT=64
__device__ float g_Be1  [32768];    // N=128,  K=256,  NT=128
__device__ float g_Be2  [65536];    // N=256,  K=256,  NT=128

// ---------------- common helpers ----------------
__device__ __forceinline__ float tf32_rna(float x) {
    uint32_t u; asm("cvt.rna.tf32.f32 %0, %1;" : "=r"(u) : "f"(x));
    return __uint_as_float(u);
}
__device__ __forceinline__ uint32_t packh2(__half l, __half h) {
    return (uint32_t)__half_as_ushort(l) | ((uint32_t)__half_as_ushort(h) << 16);
}
__device__ __forceinline__ void mma_tf32(float* c, const uint32_t* a, const uint32_t* b) {
    asm volatile("mma.sync.aligned.m16n8k8.row.col.f32.tf32.tf32.f32 "
        "{%0,%1,%2,%3}, {%4,%5,%6,%7}, {%8,%9}, {%0,%1,%2,%3};"
        : "+f"(c[0]), "+f"(c[1]), "+f"(c[2]), "+f"(c[3])
        : "r"(a[0]), "r"(a[1]), "r"(a[2]), "r"(a[3]), "r"(b[0]), "r"(b[1]));
}
__device__ __forceinline__ void mma_f16(float* c, const uint32_t* a, const uint32_t* b) {
    asm volatile("mma.sync.aligned.m16n8k16.row.col.f32.f16.f16.f32 "
        "{%0,%1,%2,%3}, {%4,%5,%6,%7}, {%8,%9}, {%0,%1,%2,%3};"
        : "+f"(c[0]), "+f"(c[1]), "+f"(c[2]), "+f"(c[3])
        : "r"(a[0]), "r"(a[1]), "r"(a[2]), "r"(a[3]), "r"(b[0]), "r"(b[1]));
}
__device__ __forceinline__ uint32_t smem_u32(const void* p) {
    uint32_t a;
    asm("{ .reg .u64 t; cvta.to.shared.u64 t, %1; cvt.u32.u64 %0, t; }" : "=r"(a) : "l"(p));
    return a;
}
__device__ __forceinline__ void cp16(uint32_t dst, const void* src) {
    asm volatile("cp.async.ca.shared.global [%0], [%1], 16;" :: "r"(dst), "l"(src));
}
#define CP_COMMIT() asm volatile("cp.async.commit_group;" ::: "memory")
#define CP_WAIT1()  asm volatile("cp.async.wait_group 1;" ::: "memory")

__device__ __forceinline__ void ins4(float* d, int* ci, float dv, int cg) {
    #pragma unroll
    for (int q = 0; q < 4; q++) {
        bool better = dv < d[q] || (dv == d[q] && cg < ci[q]);
        float td = d[q]; int ti = ci[q];
        if (better) { d[q] = dv; ci[q] = cg; dv = td; cg = ti; }
    }
}

// =====================================================================
// tf32 path (round-11 proven, bit-identical) — used ONLY for z_proj.
// =====================================================================
template<int NT>
__global__ void bprep32(const float* __restrict__ src, float* __restrict__ img,
                        int K, int ld, int trans, int total) {
    int i = blockIdx.x * 256 + threadIdx.x;
    if (i >= total) return;
    constexpr int NI = NT / 16;
    int word = i & (NT * 16 - 1);
    int rest = i / (NT * 16);
    int kb = rest % (K / 16);
    int nb = rest / (K / 16);
    int w = word & 1;
    int t = (word >> 1) & 3;
    int g = (word >> 3) & 7;
    int s = (word >> 6) & 1;
    int tl = word >> 7;
    int wn = tl / NI, ni = tl % NI;
    int n = nb * NT + wn * (NT / 2) + ni * 8 + g;
    int k = kb * 16 + s * 8 + t + w * 4;
    float x = trans ? src[(size_t)k * ld + n] : src[(size_t)n * ld + k];
    float hi = tf32_rna(x), lo = tf32_rna(x - hi);
    size_t base = (size_t)rest * (NT * 32);
    int lane = g * 4 + t;
    int off = tl * 256 + s * 128 + lane * 4 + w;
    img[base + off]     = hi;
    img[base + off + 2] = lo;
}

template<int NT>
__global__ void __launch_bounds__(256, 2)
mma_gemm32(int K, int lda, int ldc,
           const float* __restrict__ A, const float* __restrict__ Bimg,
           const float* __restrict__ bias, float* __restrict__ C) {
    constexpr int NI   = NT / 16;
    constexpr int NB   = NT * 32;
    constexpr int ABUF = 4096;
    extern __shared__ float sm[];
    const int tid = threadIdx.x;
    const int w = tid >> 5, lane = tid & 31;
    const int wm = w & 3, wn = w >> 2;
    const int g = lane >> 2, t = lane & 3;
    const int bx = blockIdx.x, by = blockIdx.y;
    const int KB = K / 16;
    const int chunkp_c = lane ^ ((lane >> 2) & 7);

    const float* Ab = A + (size_t)by * 128 * lda;
    const uint32_t smBu = smem_u32(sm + 2 * ABUF);

    const int pp = tid >> 2, prot = tid & 3;
    const int pwmi = pp >> 3, pg = pp & 7;
    const int pm = pwmi * 16 + pg;

    float acc[2][NI][4];
    #pragma unroll
    for (int mi = 0; mi < 2; mi++)
        #pragma unroll
        for (int ni = 0; ni < NI; ni++)
            #pragma unroll
            for (int q = 0; q < 4; q++) acc[mi][ni][q] = 0.f;

    float4 ra0, ra1;
    auto gloadA = [&](int st) {
        const int k0 = st * 16 + prot * 4;
        ra0 = *(const float4*)(Ab + (size_t)pm * lda + k0);
        ra1 = *(const float4*)(Ab + (size_t)(pm + 8) * lda + k0);
    };
    auto sstoreA = [&](int abuf) {
        float* AsH = sm + abuf * ABUF;
        float* AsL = AsH + 2048;
        float v0[4] = { ra0.x, ra0.y, ra0.z, ra0.w };
        float v1[4] = { ra1.x, ra1.y, ra1.z, ra1.w };
        #pragma unroll
        for (int c = 0; c < 4; c++) {
            int cc = (c + prot) & 3;
            int k  = prot * 4 + cc;
            int s  = k >> 3, u = (k >> 2) & 1, tt = k & 3;
            int chunk  = pg * 4 + tt;
            int chunkp = chunk ^ pg;
            int widx = ((pwmi * 2 + s) * 32 + chunkp) * 4 + 2 * u;
            float h0 = tf32_rna(v0[cc]), l0 = tf32_rna(v0[cc] - h0);
            float h1 = tf32_rna(v1[cc]), l1 = tf32_rna(v1[cc] - h1);
            *(float2*)(AsH + widx) = make_float2(h0, h1);
            *(float2*)(AsL + widx) = make_float2(l0, l1);
        }
    };
    auto cpB = [&](int st, int bbuf) {
        const float* src = Bimg + ((size_t)bx * KB + st) * NB + tid * (NB / 256);
        uint32_t dst = smBu + (bbuf * NB + tid * (NB / 256)) * 4;
        #pragma unroll
        for (int j = 0; j < NB / 1024; j++) cp16(dst + j * 16, src + j * 4);
    };
    auto compute = [&](int abuf, int bbuf) {
        const float* AsH = sm + abuf * ABUF;
        const float* AsL = AsH + 2048;
        const float* Bs  = sm + 2 * ABUF + bbuf * NB;
        #pragma unroll
        for (int s = 0; s < 2; s++) {
            float4 ah[2], al[2];
            #pragma unroll
            for (int mi = 0; mi < 2; mi++) {
                int q = (((wm * 2 + mi) * 2 + s) * 32 + chunkp_c) * 4;
                ah[mi] = *(const float4*)(AsH + q);
                al[mi] = *(const float4*)(AsL + q);
            }
            uint32_t a0h[4] = { __float_as_uint(ah[0].x), __float_as_uint(ah[0].y),
                                __float_as_uint(ah[0].z), __float_as_uint(ah[0].w) };
            uint32_t a1h[4] = { __float_as_uint(ah[1].x), __float_as_uint(ah[1].y),
                                __float_as_uint(ah[1].z), __float_as_uint(ah[1].w) };
            uint32_t a0l[4] = { __float_as_uint(al[0].x), __float_as_uint(al[0].y),
                                __float_as_uint(al[0].z), __float_as_uint(al[0].w) };
            uint32_t a1l[4] = { __float_as_uint(al[1].x), __float_as_uint(al[1].y),
                                __float_as_uint(al[1].z), __float_as_uint(al[1].w) };
            #pragma unroll
            for (int ni = 0; ni < NI; ni++) {
                int o = (wn * NI + ni) * 256 + s * 128 + lane * 4;
                float4 bv = *(const float4*)(Bs + o);
                uint32_t bhu[2] = { __float_as_uint(bv.x), __float_as_uint(bv.y) };
                uint32_t blu[2] = { __float_as_uint(bv.z), __float_as_uint(bv.w) };
                mma_tf32(acc[0][ni], a0h, bhu);
                mma_tf32(acc[1][ni], a1h, bhu);
                mma_tf32(acc[0][ni], a0l, bhu);
                mma_tf32(acc[1][ni], a1l, bhu);
                mma_tf32(acc[0][ni], a0h, blu);
                mma_tf32(acc[1][ni], a1h, blu);
            }
        }
    };

    cpB(0, 0); CP_COMMIT();
    if (KB > 1) cpB(1, 1);
    CP_COMMIT();
    gloadA(0);
    sstoreA(0);
    CP_WAIT1();
    __syncthreads();

    for (int st = 0; st < KB; st++) {
        if (st + 1 < KB) gloadA(st + 1);
        compute(st & 1, st % 3);
        if (st + 2 < KB) cpB(st + 2, (st + 2) % 3);
        CP_COMMIT();
        if (st + 1 < KB) sstoreA((st + 1) & 1);
        CP_WAIT1();
        __syncthreads();
    }

    #pragma unroll
    for (int mi = 0; mi < 2; mi++)
        #pragma unroll
        for (int ni = 0; ni < NI; ni++) {
            int row = by * 128 + wm * 32 + mi * 16 + g;
            int col = bx * NT + wn * (NT / 2) + ni * 8 + 2 * t;
            float b0 = bias ? bias[col]     : 0.f;
            float b1 = bias ? bias[col + 1] : 0.f;
            *(float2*)(C + (size_t)row * ldc + col) =
                make_float2(acc[mi][ni][0] + b0, acc[mi][ni][1] + b1);
            *(float2*)(C + (size_t)(row + 8) * ldc + col) =
                make_float2(acc[mi][ni][2] + b0, acc[mi][ni][3] + b1);
        }
}

// =====================================================================
// fp16 4-product path (hh+lh+hl+ll) — scores (MODE 1) + EW (MODE 0).
// =====================================================================
template<int NT>
__global__ void bprep16(const float* __restrict__ src, float* __restrict__ img,
                        int K, int ld, int trans, int total) {
    int i = blockIdx.x * 256 + threadIdx.x;
    if (i >= total) return;
    constexpr int NI = NT / 16;
    int word = i & (NT * 16 - 1);
    int rest = i / (NT * 16);
    int kb = rest % (K / 16);
    int nb = rest / (K / 16);
    int q = word & 3;
    int lane = (word >> 2) & 31;
    int tl = word >> 7;
    int g = lane >> 2, t = lane & 3;
    int wn = tl / NI, ni = tl % NI;
    int n = nb * NT + wn * (NT / 2) + ni * 8 + g;
    int k0 = kb * 16 + 2 * t + (q & 1) * 8;
    float x0 = trans ? src[(size_t)k0 * ld + n]       : src[(size_t)n * ld + k0];
    float x1 = trans ? src[(size_t)(k0 + 1) * ld + n] : src[(size_t)n * ld + k0 + 1];
    __half h0 = __float2half_rn(x0), h1 = __float2half_rn(x1);
    uint32_t u;
    if (q < 2) {
        u = packh2(h0, h1);
    } else {
        __half l0 = __float2half_rn(x0 - __half2float(h0));
        __half l1 = __float2half_rn(x1 - __half2float(h1));
        u = packh2(l0, l1);
    }
    img[(size_t)rest * (NT * 16) + word] = __uint_as_float(u);
}

template<int NT, int MODE>
__global__ void __launch_bounds__(256, 2)
mma_gemm16(int K, int lda, int ldc,
           const float* __restrict__ A, const float* __restrict__ Bimg,
           const float* __restrict__ bias, float* __restrict__ C,
           const float* __restrict__ nrp, const float* __restrict__ enp,
           int* __restrict__ candp) {
    constexpr int NI   = NT / 16;
    constexpr int NB   = NT * 16;
    constexpr int ABUF = 2048;
    extern __shared__ float sm[];
    const int tid = threadIdx.x;
    const int w = tid >> 5, lane = tid & 31;
    const int wm = w & 3, wn = w >> 2;
    const int g = lane >> 2, t = lane & 3;
    const int bx = blockIdx.x, by = blockIdx.y;
    const int KB = K / 16;
    const int chunkp_c = lane ^ ((lane >> 2) & 7);

    const float* Ab = A + (size_t)by * 128 * lda;
    const uint32_t smBu = smem_u32(sm + 2 * ABUF);

    const int pwmi = tid >> 5;
    const int pg   = (tid >> 2) & 7;
    const int prot = tid & 3;
    const int pm   = pwmi * 16 + pg;

    float acc[2][NI][4];
    #pragma unroll
    for (int mi = 0; mi < 2; mi++)
        #pragma unroll
        for (int ni = 0; ni < NI; ni++)
            #pragma unroll
            for (int q = 0; q < 4; q++) acc[mi][ni][q] = 0.f;

    float4 ra0, ra1;
    auto gloadA = [&](int st) {
        const int k0 = st * 16 + prot * 4;
        ra0 = *(const float4*)(Ab + (size_t)pm * lda + k0);
        ra1 = *(const float4*)(Ab + (size_t)(pm + 8) * lda + k0);
    };
    auto sstoreA = [&](int abuf) {
        float* AsH = sm + abuf * ABUF;
        float* AsL = AsH + 1024;
        float v0[4] = { ra0.x, ra0.y, ra0.z, ra0.w };
        float v1[4] = { ra1.x, ra1.y, ra1.z, ra1.w };
        #pragma unroll
        for (int j = 0; j < 2; j++) {
            int p = 2 * prot + j;
            int tt = p & 3, u = p >> 2;
            int chunk  = pg * 4 + tt;
            int chunkp = chunk ^ pg;
            int base = (pwmi * 32 + chunkp) * 4 + 2 * u;
            float x0 = v0[2 * j], x1 = v0[2 * j + 1];
            float y0 = v1[2 * j], y1 = v1[2 * j + 1];
            __half hx0 = __float2half_rn(x0), hx1 = __float2half_rn(x1);
            __half hy0 = __float2half_rn(y0), hy1 = __float2half_rn(y1);
            *(float2*)(AsH + base) = make_float2(
                __uint_as_float(packh2(hx0, hx1)), __uint_as_float(packh2(hy0, hy1)));
            __half lx0 = __float2half_rn(x0 - __half2float(hx0));
            __half lx1 = __float2half_rn(x1 - __half2float(hx1));
            __half ly0 = __float2half_rn(y0 - __half2float(hy0));
            __half ly1 = __float2half_rn(y1 - __half2float(hy1));
            *(float2*)(AsL + base) = make_float2(
                __uint_as_float(packh2(lx0, lx1)), __uint_as_float(packh2(ly0, ly1)));
        }
    };
    auto cpB = [&](int st, int bbuf) {
        const float* src = Bimg + ((size_t)bx * KB + st) * NB + tid * (NB / 256);
        uint32_t dst = smBu + (bbuf * NB + tid * (NB / 256)) * 4;
        #pragma unroll
        for (int j = 0; j < NB / 1024; j++) cp16(dst + j * 16, src + j * 4);
    };
    auto compute = [&](int abuf, int bbuf) {
        const float* AsH = sm + abuf * ABUF;
        const float* AsL = AsH + 1024;
        const float* Bs  = sm + 2 * ABUF + bbuf * NB;
        float4 ah[2], al[2];
        #pragma unroll
        for (int mi = 0; mi < 2; mi++) {
            int q = ((wm * 2 + mi) * 32 + chunkp_c) * 4;
            ah[mi] = *(const float4*)(AsH + q);
            al[mi] = *(const float4*)(AsL + q);
        }
        uint32_t a0h[4] = { __float_as_uint(ah[0].x), __float_as_uint(ah[0].y),
                            __float_as_uint(ah[0].z), __float_as_uint(ah[0].w) };
        uint32_t a1h[4] = { __float_as_uint(ah[1].x), __float_as_uint(ah[1].y),
                            __float_as_uint(ah[1].z), __float_as_uint(ah[1].w) };
        uint32_t a0l[4] = { __float_as_uint(al[0].x), __float_as_uint(al[0].y),
                            __float_as_uint(al[0].z), __float_as_uint(al[0].w) };
        uint32_t a1l[4] = { __float_as_uint(al[1].x), __float_as_uint(al[1].y),
                            __float_as_uint(al[1].z), __float_as_uint(al[1].w) };
        #pragma unroll
        for (int ni = 0; ni < NI; ni++) {
            int o = (wn * NI + ni) * 128 + lane * 4;
            float4 bv = *(const float4*)(Bs + o);
            uint32_t bhu[2] = { __float_as_uint(bv.x), __float_as_uint(bv.y) };
            uint32_t blu[2] = { __float_as_uint(bv.z), __float_as_uint(bv.w) };
            mma_f16(acc[0][ni], a0h, bhu);
            mma_f16(acc[1][ni], a1h, bhu);
            mma_f16(acc[0][ni], a0l, bhu);
            mma_f16(acc[1][ni], a1l, bhu);
            mma_f16(acc[0][ni], a0h, blu);
            mma_f16(acc[1][ni], a1h, blu);
            mma_f16(acc[0][ni], a0l, blu);
            mma_f16(acc[1][ni], a1l, blu);
        }
    };

    cpB(0, 0); CP_COMMIT();
    if (KB > 1) cpB(1, 1);
    CP_COMMIT();
    gloadA(0);
    sstoreA(0);
    CP_WAIT1();
    __syncthreads();

    for (int st = 0; st < KB; st++) {
        if (st + 1 < KB) gloadA(st + 1);
        compute(st & 1, st % 3);
        if (st + 2 < KB) cpB(st + 2, (st + 2) % 3);
        CP_COMMIT();
        if (st + 1 < KB) sstoreA((st + 1) & 1);
        CP_WAIT1();
        __syncthreads();
    }

    if (MODE == 0) {
        #pragma unroll
        for (int mi = 0; mi < 2; mi++)
            #pragma unroll
            for (int ni = 0; ni < NI; ni++) {
                int row = by * 128 + wm * 32 + mi * 16 + g;
                int col = bx * NT + wn * (NT / 2) + ni * 8 + 2 * t;
                float b0 = bias ? bias[col]     : 0.f;
                float b1 = bias ? bias[col + 1] : 0.f;
                *(float2*)(C + (size_t)row * ldc + col) =
                    make_float2(acc[mi][ni][0] + b0, acc[mi][ni][1] + b1);
                *(float2*)(C + (size_t)(row + 8) * ldc + col) =
                    make_float2(acc[mi][ni][2] + b0, acc[mi][ni][3] + b1);
            }
    } else {
        __syncthreads();
        float* sd = sm;
        int*   si = (int*)(sm + 1024);
        #pragma unroll
        for (int mi = 0; mi < 2; mi++)
            #pragma unroll
            for (int h = 0; h < 2; h++) {
                int rloc = wm * 32 + mi * 16 + h * 8 + g;
                float nr = nrp[by * 128 + rloc];
                float d[4] = { 3.4e38f, 3.4e38f, 3.4e38f, 3.4e38f };
                int   ci[4] = { 0, 0, 0, 0 };
                #pragma unroll
                for (int ni = 0; ni < NI; ni++)
                    #pragma unroll
                    for (int cc = 0; cc < 2; cc++) {
                        int cg = bx * NT + wn * (NT / 2) + ni * 8 + 2 * t + cc;
                        float dd = (nr - 2.f * acc[mi][ni][h * 2 + cc]) + enp[cg];
                        ins4(d, ci, dd, cg);
                    }
                #pragma unroll
                for (int o = 1; o < 4; o <<= 1) {
                    float od[4]; int oi[4];
                    #pragma unroll
                    for (int q = 0; q < 4; q++) {
                        od[q] = __shfl_xor_sync(0xffffffffu, d[q], o);
                        oi[q] = __shfl_xor_sync(0xffffffffu, ci[q], o);
                    }
                    #pragma unroll
                    for (int q = 0; q < 4; q++) ins4(d, ci, od[q], oi[q]);
                }
                if (t == 0) {
                    int base = (wn * 128 + rloc) * 4;
                    #pragma unroll
                    for (int q = 0; q < 4; q++) { sd[base + q] = d[q]; si[base + q] = ci[q]; }
                }
            }
        __syncthreads();
        if (tid < 128) {
            float d[4]; int ci[4];
            #pragma unroll
            for (int q = 0; q < 4; q++) { d[q] = sd[tid * 4 + q]; ci[q] = si[tid * 4 + q]; }
            #pragma unroll
            for (int q = 0; q < 4; q++)
                ins4(d, ci, sd[(128 + tid) * 4 + q], si[(128 + tid) * 4 + q]);
            size_t tok = (size_t)by * 128 + tid;
            #pragma unroll
            for (int q = 0; q < 4; q++)
                candp[(size_t)(bx * 4 + q) * BN_TOK + tok] = ci[q];
        }
    }
}

// ---------------- concat codebooks into [512 x 256], zero-padded ----------
__global__ void ecat_kernel(const float* __restrict__ e0, const float* __restrict__ e1,
                            const float* __restrict__ e2) {
    int i = blockIdx.x * 256 + threadIdx.x;
    int row = i >> 8, col = i & 255;
    float v = 0.f;
    if (row < 64)        v = e0[row * 256 + col];
    else if (row < 192)  v = e1[(row - 64) * 256 + col];
    else if (row < 448)  v = e2[(row - 192) * 256 + col];
    g_ecat[i] = v;
}

// ---------------- codebook squared norms ----------------
__device__ __forceinline__ float dot256d(const float* a, const float* b) {
    const float4* a4 = (const float4*)a; const float4* b4 = (const float4*)b;
    float s = 0.f;
    #pragma unroll 8
    for (int i = 0; i < 64; i++) {
        float4 x = a4[i], y = b4[i];
        s = fmaf(x.x, y.x, s); s = fmaf(x.y, y.y, s);
        s = fmaf(x.z, y.z, s); s = fmaf(x.w, y.w, s);
    }
    return s;
}
__global__ void norm_kernel(const float* __restrict__ e0, const float* __restrict__ e1,
                            const float* __restrict__ e2) {
    int j = blockIdx.x * blockDim.x + threadIdx.x;
    if (j >= 448) return;
    const float* r;
    if (j < KC0)            r = e0 + j * PDIM;
    else if (j < KC0 + KC1) r = e1 + (j - KC0) * PDIM;
    else                    r = e2 + (j - KC0 - KC1) * PDIM;
    g_enorm[j] = dot256d(r, r);
}

// ---------------- per-token ||z_proj||^2 ----------------
__global__ void rownorm_kernel() {
    int tk = blockIdx.x * 8 + (threadIdx.x >> 5);
    int lane = threadIdx.x & 31;
    const float4* row = (const float4*)(g_zproj + (size_t)tk * PDIM);
    float s = 0.f;
    #pragma unroll
    for (int i = lane; i < 64; i += 32) {
        float4 v = row[i];
        s = fmaf(v.x, v.x, s); s = fmaf(v.y, v.y, s);
        s = fmaf(v.z, v.z, s); s = fmaf(v.w, v.w, s);
    }
    #pragma unroll
    for (int o = 16; o; o >>= 1) s += __shfl_down_sync(0xffffffffu, s, o);
    if (lane == 0) g_nr[tk] = s;
}

// ---------------- refine: exact fp32 re-rank of candidates + residual update
template<int NC, int MODE>
__global__ void refine_kernel(const float* __restrict__ Rin, float* __restrict__ Rout,
                              const float* __restrict__ emb, int enoff, int level,
                              const int* __restrict__ candp, float* __restrict__ out) {
    const int warp = threadIdx.x >> 5, lane = threadIdx.x & 31;
    const int tk = blockIdx.x * 8 + warp;
    const float4* r4 = (const float4*)(Rin + (size_t)tk * PDIM);
    float4 ra = r4[lane * 2], rb = r4[lane * 2 + 1];
    float bestd = 3.4e38f; int bestc = 0x7fffffff;
    #pragma unroll
    for (int j = 0; j < NC; j++) {
        const int cj = candp[(size_t)j * BN_TOK + tk];
        const float4* e4 = (const float4*)(emb + (size_t)cj * PDIM);
        float4 ea = e4[lane * 2], eb = e4[lane * 2 + 1];
        float s = 0.f;
        s = fmaf(ra.x, ea.x, s); s = fmaf(ra.y, ea.y, s);
        s = fmaf(ra.z, ea.z, s); s = fmaf(ra.w, ea.w, s);
        s = fmaf(rb.x, eb.x, s); s = fmaf(rb.y, eb.y, s);
        s = fmaf(rb.z, eb.z, s); s = fmaf(rb.w, eb.w, s);
        #pragma unroll
        for (int o = 16; o; o >>= 1) s += __shfl_xor_sync(0xffffffffu, s, o);
        float d = __fadd_rn(g_enorm[enoff + cj], __fmul_rn(-2.f, s));
        if (d < bestd || (d == bestd && cj < bestc)) { bestd = d; bestc = cj; }
    }
    const float4* e4 = (const float4*)(emb + (size_t)bestc * PDIM);
    float4 ea = e4[lane * 2], eb = e4[lane * 2 + 1];
    float4 na, nb;
    na.x = ra.x - ea.x; na.y = ra.y - ea.y; na.z = ra.z - ea.z; na.w = ra.w - ea.w;
    nb.x = rb.x - eb.x; nb.y = rb.y - eb.y; nb.z = rb.z - eb.z; nb.w = rb.w - eb.w;
    float ns = 0.f;
    ns = fmaf(na.x, na.x, ns); ns = fmaf(na.y, na.y, ns);
    ns = fmaf(na.z, na.z, ns); ns = fmaf(na.w, na.w, ns);
    ns = fmaf(nb.x, nb.x, ns); ns = fmaf(nb.y, nb.y, ns);
    ns = fmaf(nb.z, nb.z, ns); ns = fmaf(nb.w, nb.w, ns);
    #pragma unroll
    for (int o = 16; o; o >>= 1) ns += __shfl_xor_sync(0xffffffffu, ns, o);

    if (MODE != 2) {
        float4* ro = (float4*)(Rout + (size_t)tk * PDIM);
        ro[lane * 2] = na; ro[lane * 2 + 1] = nb;
    }
    if (lane == 0) {
        g_nr[tk] = ns;
        if (MODE == 0) g_dmin[tk] = ns; else g_dmin[tk] += ns;
        g_idx[level * BN_TOK + tk] = bestc;
        out[OUT_IDX + level * BN_TOK + tk] = (float)bestc;
    }
}

// ---------------- output gather-add ----------------
__global__ void gather_out(const float* __restrict__ bias, float* __restrict__ out) {
    const int tk = blockIdx.x;
    const int j  = threadIdx.x;
    const int i0 = g_idx[tk], i1 = g_idx[BN_TOK + tk], i2 = g_idx[2 * BN_TOK + tk];
    const float4* r0 = (const float4*)(g_EW + (size_t)i0 * DDIM);
    const float4* r1 = (const float4*)(g_EW + (size_t)(64 + i1) * DDIM);
    const float4* r2 = (const float4*)(g_EW + (size_t)(192 + i2) * DDIM);
    float4 a = r0[j], b = r1[j], c = r2[j];
    float4 bb = ((const float4*)bias)[j];
    float4 v;
    v.x = a.x + b.x + c.x + bb.x;
    v.y = a.y + b.y + c.y + bb.y;
    v.z = a.z + b.z + c.z + bb.z;
    v.w = a.w + b.w + c.w + bb.w;
    ((float4*)(out + (size_t)tk * DDIM))[j] = v;
}

// ---------------- loss finalize ----------------
__global__ void loss_final(float* __restrict__ out) {
    __shared__ float red[256];
    const int p = threadIdx.x;
    float s = 0.f;
    for (int i = p; i < BN_TOK; i += 256) s += g_dmin[i];
    red[p] = s;
    __syncthreads();
    for (int st = 128; st; st >>= 1) {
        if (p < st) red[p] += red[p + st];
        __syncthreads();
    }
    if (p == 0)
        out[OUT_LOSS] = 0.25f * red[0] / ((float)BN_TOK * (float)PDIM * 3.f);
}

// ---------------- launcher ----------------
extern "C" void kernel_launch(void* const* d_in, const int* in_sizes, int n_in,
                              void* d_out, int out_size) {
    const float* z     = (const float*)d_in[0];
    const float* W_in  = (const float*)d_in[1];
    const float* b_in  = (const float*)d_in[2];
    const float* W_out = (const float*)d_in[3];
    const float* b_out = (const float*)d_in[4];
    const float* e0    = (const float*)d_in[5];
    const float* e1    = (const float*)d_in[6];
    const float* e2    = (const float*)d_in[7];
    float* out = (float*)d_out;

    float *zproj, *R, *nr, *enorm, *ecat, *ew;
    float *bwin, *bwout, *be0, *be1, *be2;
    int *cand;
    cudaGetSymbolAddress((void**)&zproj, g_zproj);
    cudaGetSymbolAddress((void**)&R,     g_R);
    cudaGetSymbolAddress((void**)&nr,    g_nr);
    cudaGetSymbolAddress((void**)&enorm, g_enorm);
    cudaGetSymbolAddress((void**)&cand,  g_cand);
    cudaGetSymbolAddress((void**)&ecat,  g_ecat);
    cudaGetSymbolAddress((void**)&ew,    g_EW);
    cudaGetSymbolAddress((void**)&bwin,  g_BWin);
    cudaGetSymbolAddress((void**)&bwout, g_BWout);
    cudaGetSymbolAddress((void**)&be0,   g_Be0);
    cudaGetSymbolAddress((void**)&be1,   g_Be1);
    cudaGetSymbolAddress((void**)&be2,   g_Be2);

    const int SM32_128 = (2 * 4096 + 3 * 128 * 32) * 4;   // 81920 (tf32)
    const int SM16_128 = (2 * 2048 + 3 * 128 * 16) * 4;   // 40960 (fp16)
    const int SM16_64  = (2 * 2048 + 3 * 64 * 16) * 4;    // 28672 (fp16)
    cudaFuncSetAttribute(mma_gemm32<128>,    cudaFuncAttributeMaxDynamicSharedMemorySize, SM32_128);
    cudaFuncSetAttribute(mma_gemm16<128, 0>, cudaFuncAttributeMaxDynamicSharedMemorySize, SM16_128);
    cudaFuncSetAttribute(mma_gemm16<128, 1>, cudaFuncAttributeMaxDynamicSharedMemorySize, SM16_128);
    cudaFuncSetAttribute(mma_gemm16<64, 1>,  cudaFuncAttributeMaxDynamicSharedMemorySize, SM16_64);

    // operand prep + concat + norms
    bprep32<128><<<(256 * 1408) / 256, 256>>>(W_in,  bwin,  1408, 256,  1, 256 * 1408);
    bprep16<128><<<(1408 * 256) / 256, 256>>>(W_out, bwout, 256,  1408, 1, 1408 * 256);
    bprep16<64> <<<(64 * 256) / 256,   256>>>(e0,    be0,   256,  256,  0, 64 * 256);
    bprep16<128><<<(128 * 256) / 256,  256>>>(e1,    be1,   256,  256,  0, 128 * 256);
    bprep16<128><<<(256 * 256) / 256,  256>>>(e2,    be2,   256,  256,  0, 256 * 256);
    ecat_kernel<<<512, 256>>>(e0, e1, e2);
    norm_kernel<<<2, 256>>>(e0, e1, e2);

    // EW = ecat @ W_out  (fp16x4; output values only)
    mma_gemm16<128, 0><<<dim3(11, 4), 256, SM16_128>>>(
        PDIM, PDIM, DDIM, ecat, bwout, nullptr, ew, nullptr, nullptr, nullptr);

    // z_proj = z @ W_in + b_in  (tf32x3 — bit-identical to round 11)
    mma_gemm32<128><<<dim3(2, BN_TOK / 128), 256, SM32_128>>>(
        DDIM, DDIM, PDIM, z, bwin, b_in, zproj);
    rownorm_kernel<<<BN_TOK / 8, 256>>>();

    // level 0 (64 codes) -> 4 candidates (fp16x4)
    mma_gemm16<64, 1><<<dim3(1, BN_TOK / 128), 256, SM16_64>>>(
        PDIM, PDIM, 0, zproj, be0, nullptr, nullptr, nr, enorm, cand);
    refine_kernel<4, 0><<<BN_TOK / 8, 256>>>(zproj, R, e0, 0, 0, cand, out);

    // level 1 (128 codes) -> 4 candidates
    mma_gemm16<128, 1><<<dim3(1, BN_TOK / 128), 256, SM16_128>>>(
        PDIM, PDIM, 0, R, be1, nullptr, nullptr, nr, enorm + KC0, cand);
    refine_kernel<4, 1><<<BN_TOK / 8, 256>>>(R, R, e1, KC0, 1, cand, out);

    // level 2 (256 codes; two N-blocks) -> 8 candidates
    mma_gemm16<128, 1><<<dim3(2, BN_TOK / 128), 256, SM16_128>>>(
        PDIM, PDIM, 0, R, be2, nullptr, nullptr, nr, enorm + KC0 + KC1, cand);
    refine_kernel<8, 2><<<BN_TOK / 8, 256>>>(R, nullptr, e2, KC0 + KC1, 2, cand, out);

    loss_final<<<1, 256>>>(out);

    // z_q_out via gather-add of precomputed EW rows
    gather_out<<<BN_TOK, 352>>>(b_out, out);
}